// round 1
// baseline (speedup 1.0000x reference)
#include <cuda_runtime.h>
#include <stdint.h>

// ---------------------------------------------------------------------------
// DenseCRF mean-field, exploiting:
//   * exact separability of the spatial Gaussian kernel (3 x 1-D convs)
//   * extreme color-sparsity of the bilateral kernel (beta=3, uniform colors)
// Everything per-launch recomputed; no atomics on floats -> deterministic.
// ---------------------------------------------------------------------------

#define NPIX   8192          // D*H*W = 8*32*32
#define DD     8
#define HH     32
#define WW     32
#define LL     21
#define LP     24            // padded label count
#define NITER  5
#define NBIN   12
#define NBIN3  1728          // 12^3
#define CAP    128           // max sparse neighbors per pixel (expected ~17)
#define ECUT   23.0f         // drop bilateral terms with exponent > 23 (k < 1e-10)

#define SA (1.0f/(160.0f*1.41421356237f))   // pos scale: 1/(alpha*sqrt(2))
#define SB (1.0f/(3.0f*1.41421356237f))     // color scale: 1/(beta*sqrt(2))

// ------------------------------- scratch -----------------------------------
__device__ float4 g_feat[NPIX*2];      // [pos*SA x3 | col*SB x3 | 0 0]
__device__ int    g_binid[NPIX];
__device__ int    g_binstart[NBIN3];
__device__ int    g_bincnt[NBIN3];
__device__ int    g_binpts[NPIX];
__device__ int    g_nidx[NPIX*CAP];    // sparse bilateral neighbor indices
__device__ float  g_nval[NPIX*CAP];    // sparse bilateral kernel values
__device__ int    g_ncnt[NPIX];
__device__ float  g_nbi[NPIX];         // bilateral normalizer (row sum)
__device__ float  g_qT[NPIX*LP];       // probabilities, pixel-major padded
__device__ float  g_t1[NPIX*LP];       // after z-conv
__device__ float  g_t2[NPIX*LP];       // after y-conv
__device__ float  g_bi[NPIX*LP];       // bilateral message (un-normalized)
__device__ float  g_CWsp[LL*LL];       // compat @ spatial_weights
__device__ float  g_CWbi[LL*LL];       // compat @ bilateral_weights
__device__ float  g_kg[32*32];         // 1-D Gaussian LUT exp(-0.5*((a-b)/3)^2)
__device__ float  g_sz[8];             // tap sums (z)
__device__ float  g_syx[32];           // tap sums (y / x)

// ---------------------------------------------------------------------------
// Setup: CW matrices, Gaussian LUT + sums, scaled features, color-bin CSR
// (counts via integer shared atomics, scatter via deterministic warp ranking)
// ---------------------------------------------------------------------------
__global__ void k_setup(const float* __restrict__ image,
                        const float* __restrict__ Wsp,
                        const float* __restrict__ Wbi,
                        const float* __restrict__ C)
{
    __shared__ int scnt[NBIN3];
    __shared__ int csum[28];
    const int tid = threadIdx.x;                 // 1024 threads

    // CWsp = C @ Wsp, CWbi = C @ Wbi   (21x21 each)
    for (int e = tid; e < LL*LL; e += 1024) {
        int l = e / LL, m = e - l*LL;
        float a = 0.f, b = 0.f;
        for (int k = 0; k < LL; k++) {
            float c = C[l*LL + k];
            a += c * Wsp[k*LL + m];
            b += c * Wbi[k*LL + m];
        }
        g_CWsp[e] = a; g_CWbi[e] = b;
    }
    // 1-D Gaussian LUT
    {
        int a = tid >> 5, b = tid & 31;
        float d = (float)(a - b) * (1.0f/3.0f);
        g_kg[tid] = __expf(-0.5f * d * d);
    }
    for (int e = tid; e < NBIN3; e += 1024) scnt[e] = 0;
    __syncthreads();

    if (tid < 32) {
        float s = 0.f;
        for (int b = 0; b < 32; b++) s += g_kg[tid*32 + b];
        g_syx[tid] = s;
    } else if (tid < 40) {
        int a = tid - 32;
        float s = 0.f;
        for (int b = 0; b < 8; b++) s += g_kg[a*32 + b];
        g_sz[a] = s;
    }

    // scaled features + bin ids + bin counts
    for (int i = tid; i < NPIX; i += 1024) {
        int z = i >> 10, y = (i >> 5) & 31, x = i & 31;
        float c0 = image[i], c1 = image[NPIX + i], c2 = image[2*NPIX + i];
        g_feat[i*2]   = make_float4((float)z*SA, (float)y*SA, (float)x*SA, c0*SB);
        g_feat[i*2+1] = make_float4(c1*SB, c2*SB, 0.f, 0.f);
        int b0 = (int)(c0 * (12.0f/255.0f)); b0 = b0 < 0 ? 0 : (b0 > 11 ? 11 : b0);
        int b1 = (int)(c1 * (12.0f/255.0f)); b1 = b1 < 0 ? 0 : (b1 > 11 ? 11 : b1);
        int b2 = (int)(c2 * (12.0f/255.0f)); b2 = b2 < 0 ? 0 : (b2 > 11 ? 11 : b2);
        int bin = (b0*NBIN + b1)*NBIN + b2;
        g_binid[i] = bin;
        atomicAdd(&scnt[bin], 1);
    }
    __syncthreads();

    // prefix: 27 chunks of 64
    if (tid < 27) {
        int s = 0;
        for (int k = 0; k < 64; k++) s += scnt[tid*64 + k];
        csum[tid] = s;
    }
    __syncthreads();
    if (tid == 0) {
        int s = 0;
        for (int c = 0; c < 27; c++) { int t = csum[c]; csum[c] = s; s += t; }
    }
    __syncthreads();
    for (int b = tid; b < NBIN3; b += 1024) {
        int chunk = b >> 6;
        int s = csum[chunk];
        for (int k = chunk*64; k < b; k++) s += scnt[k];
        g_binstart[b] = s;
        g_bincnt[b]   = scnt[b];
    }
    __syncthreads();
    for (int e = tid; e < NBIN3; e += 1024) scnt[e] = 0;  // reuse as cursors
    __syncthreads();

    // deterministic scatter: warp 0 processes pixels in fixed order
    if (tid < 32) {
        for (int base = 0; base < NPIX; base += 32) {
            int i = base + tid;
            int b = g_binid[i];
            unsigned m = __match_any_sync(0xffffffffu, b);
            int rank = __popc(m & ((1u << tid) - 1u));
            int leader = __ffs(m) - 1;
            int cur = scnt[b];
            g_binpts[g_binstart[b] + cur + rank] = i;
            __syncwarp();
            if (tid == leader) scnt[b] = cur + __popc(m);
            __syncwarp();
        }
    }
}

// ---------------------------------------------------------------------------
// Build sparse bilateral rows: one warp per pixel scans 27 neighbor bins.
// ---------------------------------------------------------------------------
__global__ void k_build()
{
    int gw   = (blockIdx.x * blockDim.x + threadIdx.x) >> 5;
    int lane = threadIdx.x & 31;
    if (gw >= NPIX) return;
    const int i = gw;
    float4 fa = g_feat[i*2], fb = g_feat[i*2+1];
    int bin = g_binid[i];
    int b0 = bin / 144, r = bin - b0*144, b1 = r / 12, b2 = r - b1*12;

    int   cnt = 0;
    float nb  = 0.f;
    int d0lo = b0 > 0 ? b0-1 : 0, d0hi = b0 < 11 ? b0+1 : 11;
    int d1lo = b1 > 0 ? b1-1 : 0, d1hi = b1 < 11 ? b1+1 : 11;
    int d2lo = b2 > 0 ? b2-1 : 0, d2hi = b2 < 11 ? b2+1 : 11;

    for (int d0 = d0lo; d0 <= d0hi; d0++)
    for (int d1 = d1lo; d1 <= d1hi; d1++)
    for (int d2 = d2lo; d2 <= d2hi; d2++) {
        int nbin = (d0*NBIN + d1)*NBIN + d2;
        int s = g_binstart[nbin], e = s + g_bincnt[nbin];
        for (int base = s; base < e; base += 32) {
            int idx = base + lane;
            float ev = 1e30f; int j = -1;
            if (idx < e) {
                j = g_binpts[idx];
                float4 ga = g_feat[j*2], gb = g_feat[j*2+1];
                float u0 = fa.x-ga.x, u1 = fa.y-ga.y, u2 = fa.z-ga.z;
                float u3 = fa.w-ga.w, u4 = fb.x-gb.x, u5 = fb.y-gb.y;
                ev = u0*u0 + u1*u1 + u2*u2 + u3*u3 + u4*u4 + u5*u5;
            }
            bool acc = (ev <= ECUT);
            unsigned m = __ballot_sync(0xffffffffu, acc);
            if (acc) {
                int off = cnt + __popc(m & ((1u << lane) - 1u));
                if (off < CAP) {
                    float kv = __expf(-ev);
                    g_nidx[i*CAP + off] = j;
                    g_nval[i*CAP + off] = kv;
                    nb += kv;
                }
            }
            cnt += __popc(m);
        }
    }
    for (int o = 16; o; o >>= 1) nb += __shfl_xor_sync(0xffffffffu, nb, o);
    if (cnt > CAP) cnt = CAP;
    if (lane == 0) { g_ncnt[i] = cnt; g_nbi[i] = nb; }
}

// ---------------------------------------------------------------------------
// Initial softmax: logits (L,N) -> qT (N,LP)
// ---------------------------------------------------------------------------
__global__ void k_softmax0(const float* __restrict__ logits)
{
    int i = blockIdx.x * blockDim.x + threadIdx.x;    // 8192
    float v[LL];
    float mx = -1e30f;
    #pragma unroll
    for (int l = 0; l < LL; l++) { v[l] = logits[l*NPIX + i]; mx = fmaxf(mx, v[l]); }
    float s = 0.f;
    #pragma unroll
    for (int l = 0; l < LL; l++) { v[l] = __expf(v[l] - mx); s += v[l]; }
    float inv = 1.0f / s;
    #pragma unroll
    for (int l = 0; l < LL; l++) g_qT[i*LP + l] = v[l] * inv;
    g_qT[i*LP + 21] = 0.f; g_qT[i*LP + 22] = 0.f; g_qT[i*LP + 23] = 0.f;
}

// ---------------------------------------------------------------------------
// Phase B: z-conv (blocks [0,768)) + sparse bilateral gather (blocks [768,1792))
// Both only read g_qT, so they run in one launch.
// ---------------------------------------------------------------------------
__global__ void k_zb()
{
    if (blockIdx.x < 768) {
        int e = blockIdx.x * 256 + threadIdx.x;       // < NPIX*LP
        int i = e / LP, l = e - i*LP;
        int zbase = i & 1023;
        int z = i >> 10;
        float acc = 0.f;
        #pragma unroll
        for (int zp = 0; zp < DD; zp++)
            acc += g_kg[z*32 + zp] * g_qT[((zp << 10) | zbase)*LP + l];
        g_t1[e] = acc;
    } else {
        int w    = ((blockIdx.x - 768) * 256 + threadIdx.x) >> 5;  // pixel
        int lane = threadIdx.x & 31;
        int cnt  = g_ncnt[w];
        float acc = 0.f;
        const int*   ip = &g_nidx[w*CAP];
        const float* vp = &g_nval[w*CAP];
        for (int n = 0; n < cnt; n++) {
            int j   = ip[n];         // warp-uniform -> broadcast
            float k = vp[n];
            if (lane < LP) acc += k * g_qT[j*LP + lane];
        }
        if (lane < LP) g_bi[w*LP + lane] = acc;
    }
}

// ---------------------------------------------------------------------------
// Phase C: y-conv. CTA per (z,x) column, threads (y,l).
// ---------------------------------------------------------------------------
__global__ void k_convy()
{
    __shared__ float sh[32*LP];
    int z = blockIdx.x >> 5, x = blockIdx.x & 31;
    int tid = threadIdx.x;                 // 768
    int y = tid / LP, l = tid - y*LP;
    int i = (z << 10) + (y << 5) + x;
    sh[tid] = g_t1[i*LP + l];
    __syncthreads();
    float acc = 0.f;
    const float* kr = &g_kg[y*32];
    #pragma unroll 8
    for (int yp = 0; yp < 32; yp++) acc += kr[yp] * sh[yp*LP + l];
    g_t2[i*LP + l] = acc;
}

// ---------------------------------------------------------------------------
// Phase D: x-conv + normalize + L x L mixing + cur = unary + msg + softmax.
// CTA per (z,y) row, threads (x,l). Writes qT for next iter; on last iter
// also writes the final probabilities to d_out (label-major).
// ---------------------------------------------------------------------------
__global__ void k_final(const float* __restrict__ unary, float* __restrict__ out,
                        int last)
{
    __shared__ float sh[32*LP];
    __shared__ float sc[32*LP];
    __shared__ float wsp[LL*LL], wbi[LL*LL];
    int z = blockIdx.x >> 5, y = blockIdx.x & 31;
    int tid = threadIdx.x;                 // 768
    int x = tid / LP, l = tid - x*LP;
    for (int e = tid; e < LL*LL; e += 768) { wsp[e] = g_CWsp[e]; wbi[e] = g_CWbi[e]; }
    int i = (z << 10) + (y << 5) + x;
    sh[tid] = g_t2[i*LP + l];
    __syncthreads();

    float sp = 0.f;
    {
        const float* kr = &g_kg[x*32];
        #pragma unroll 8
        for (int xp = 0; xp < 32; xp++) sp += kr[xp] * sh[xp*LP + l];
    }
    float nsp = g_sz[z] * g_syx[y] * g_syx[x];
    float nbi = g_nbi[i];
    __syncthreads();
    sh[tid] = sp / nsp;
    sc[tid] = g_bi[i*LP + l] / nbi;
    __syncthreads();

    float cur = -1e30f;
    if (l < LL) {
        float msg = 0.f;
        #pragma unroll
        for (int m = 0; m < LL; m++)
            msg += wsp[l*LL + m] * sh[x*LP + m] + wbi[l*LL + m] * sc[x*LP + m];
        cur = unary[l*NPIX + i] + msg;
    }
    __syncthreads();
    sh[tid] = cur;
    __syncthreads();

    float mx = -1e30f;
    #pragma unroll
    for (int m = 0; m < LL; m++) mx = fmaxf(mx, sh[x*LP + m]);
    float se = 0.f;
    #pragma unroll
    for (int m = 0; m < LL; m++) se += __expf(sh[x*LP + m] - mx);
    float q = __expf(cur - mx) / se;
    g_qT[i*LP + l] = (l < LL) ? q : 0.f;
    if (last && l < LL) out[l*NPIX + i] = q;
}

// ---------------------------------------------------------------------------
extern "C" void kernel_launch(void* const* d_in, const int* in_sizes, int n_in,
                              void* d_out, int out_size)
{
    (void)in_sizes; (void)n_in; (void)out_size;
    const float* image  = (const float*)d_in[0];
    const float* logits = (const float*)d_in[1];
    const float* unary  = (const float*)d_in[2];
    const float* Wsp    = (const float*)d_in[3];
    const float* Wbi    = (const float*)d_in[4];
    const float* C      = (const float*)d_in[5];
    float* out = (float*)d_out;

    k_setup<<<1, 1024>>>(image, Wsp, Wbi, C);
    k_build<<<1024, 256>>>();
    k_softmax0<<<32, 256>>>(logits);
    for (int it = 0; it < NITER; it++) {
        k_zb<<<1792, 256>>>();
        k_convy<<<256, 768>>>();
        k_final<<<256, 768>>>(unary, out, it == NITER - 1);
    }
}

// round 2
// speedup vs baseline: 1.1579x; 1.1579x over previous
#include <cuda_runtime.h>
#include <stdint.h>

// ---------------------------------------------------------------------------
// DenseCRF mean-field:
//   * exact separability of the spatial Gaussian kernel (3 x 1-D convs)
//   * extreme color-sparsity of the bilateral kernel (beta=3, uniform colors)
// R2: cooperative per-bin sparse build (226MB -> 3.5MB gather traffic),
//     single-exp softmax in k_final, unrolled bilateral gather.
// ---------------------------------------------------------------------------

#define NPIX   8192          // D*H*W = 8*32*32
#define DD     8
#define LL     21
#define LP     24            // padded label count
#define NITER  5
#define NBIN   12
#define NBIN3  1728          // 12^3
#define CAP    128           // max sparse neighbors per pixel (expected ~17)
#define SCAP   2048          // candidate staging capacity per bin neighborhood
#define ECUT   23.0f         // drop bilateral terms with exponent > 23 (k < 1e-10)

#define SA (1.0f/(160.0f*1.41421356237f))   // pos scale: 1/(alpha*sqrt(2))
#define SB (1.0f/(3.0f*1.41421356237f))     // color scale: 1/(beta*sqrt(2))

// ------------------------------- scratch -----------------------------------
__device__ float4 g_col[NPIX];         // scaled colors (c*SB), w unused
__device__ int    g_binid[NPIX];
__device__ int    g_binstart[NBIN3];
__device__ int    g_bincnt[NBIN3];
__device__ int    g_binpts[NPIX];
__device__ int    g_nidx[NPIX*CAP];    // sparse bilateral neighbor indices
__device__ float  g_nval[NPIX*CAP];    // sparse bilateral kernel values
__device__ int    g_ncnt[NPIX];
__device__ float  g_nbi[NPIX];         // bilateral normalizer (row sum)
__device__ float  g_qT[NPIX*LP];       // probabilities, pixel-major padded
__device__ float  g_t1[NPIX*LP];       // after z-conv
__device__ float  g_t2[NPIX*LP];       // after y-conv
__device__ float  g_bi[NPIX*LP];       // bilateral message (un-normalized)
__device__ float  g_CWsp[LL*LL];       // compat @ spatial_weights
__device__ float  g_CWbi[LL*LL];       // compat @ bilateral_weights
__device__ float  g_kg[32*32];         // 1-D Gaussian LUT exp(-0.5*((a-b)/3)^2)
__device__ float  g_sz[8];             // tap sums (z)
__device__ float  g_syx[32];           // tap sums (y / x)

// ---------------------------------------------------------------------------
// Setup: CW matrices, Gaussian LUT + sums, scaled colors, color-bin CSR
// (counts via integer shared atomics, scatter via deterministic warp ranking)
// ---------------------------------------------------------------------------
__global__ void k_setup(const float* __restrict__ image,
                        const float* __restrict__ Wsp,
                        const float* __restrict__ Wbi,
                        const float* __restrict__ C)
{
    __shared__ int scnt[NBIN3];
    __shared__ int csum[28];
    const int tid = threadIdx.x;                 // 1024 threads

    // CWsp = C @ Wsp, CWbi = C @ Wbi   (21x21 each)
    for (int e = tid; e < LL*LL; e += 1024) {
        int l = e / LL, m = e - l*LL;
        float a = 0.f, b = 0.f;
        for (int k = 0; k < LL; k++) {
            float c = C[l*LL + k];
            a += c * Wsp[k*LL + m];
            b += c * Wbi[k*LL + m];
        }
        g_CWsp[e] = a; g_CWbi[e] = b;
    }
    // 1-D Gaussian LUT
    {
        int a = tid >> 5, b = tid & 31;
        float d = (float)(a - b) * (1.0f/3.0f);
        g_kg[tid] = __expf(-0.5f * d * d);
    }
    for (int e = tid; e < NBIN3; e += 1024) scnt[e] = 0;
    __syncthreads();

    if (tid < 32) {
        float s = 0.f;
        for (int b = 0; b < 32; b++) s += g_kg[tid*32 + b];
        g_syx[tid] = s;
    } else if (tid < 40) {
        int a = tid - 32;
        float s = 0.f;
        for (int b = 0; b < 8; b++) s += g_kg[a*32 + b];
        g_sz[a] = s;
    }

    // scaled colors + bin ids + bin counts
    for (int i = tid; i < NPIX; i += 1024) {
        float c0 = image[i], c1 = image[NPIX + i], c2 = image[2*NPIX + i];
        g_col[i] = make_float4(c0*SB, c1*SB, c2*SB, 0.f);
        int b0 = (int)(c0 * (12.0f/255.0f)); b0 = b0 < 0 ? 0 : (b0 > 11 ? 11 : b0);
        int b1 = (int)(c1 * (12.0f/255.0f)); b1 = b1 < 0 ? 0 : (b1 > 11 ? 11 : b1);
        int b2 = (int)(c2 * (12.0f/255.0f)); b2 = b2 < 0 ? 0 : (b2 > 11 ? 11 : b2);
        int bin = (b0*NBIN + b1)*NBIN + b2;
        g_binid[i] = bin;
        atomicAdd(&scnt[bin], 1);
    }
    __syncthreads();

    // prefix: 27 chunks of 64
    if (tid < 27) {
        int s = 0;
        for (int k = 0; k < 64; k++) s += scnt[tid*64 + k];
        csum[tid] = s;
    }
    __syncthreads();
    if (tid == 0) {
        int s = 0;
        for (int c = 0; c < 27; c++) { int t = csum[c]; csum[c] = s; s += t; }
    }
    __syncthreads();
    for (int b = tid; b < NBIN3; b += 1024) {
        int chunk = b >> 6;
        int s = csum[chunk];
        for (int k = chunk*64; k < b; k++) s += scnt[k];
        g_binstart[b] = s;
        g_bincnt[b]   = scnt[b];
    }
    __syncthreads();
    for (int e = tid; e < NBIN3; e += 1024) scnt[e] = 0;  // reuse as cursors
    __syncthreads();

    // deterministic scatter: warp 0 processes pixels in fixed order
    if (tid < 32) {
        for (int base = 0; base < NPIX; base += 32) {
            int i = base + tid;
            int b = g_binid[i];
            unsigned m = __match_any_sync(0xffffffffu, b);
            int rank = __popc(m & ((1u << tid) - 1u));
            int leader = __ffs(m) - 1;
            int cur = scnt[b];
            g_binpts[g_binstart[b] + cur + rank] = i;
            __syncwarp();
            if (tid == leader) scnt[b] = cur + __popc(m);
            __syncwarp();
        }
    }
}

// ---------------------------------------------------------------------------
// Build sparse bilateral rows, cooperatively per bin: stage the shared 27-bin
// candidate neighborhood in SMEM once, then each warp tests one member pixel.
// Positions recovered from pixel index (no feature gather).
// ---------------------------------------------------------------------------
__global__ void k_build()
{
    __shared__ int   sj[SCAP];
    __shared__ float s0[SCAP], s1[SCAP], s2[SCAP];
    const int b   = blockIdx.x;
    const int cnt = g_bincnt[b];
    if (cnt == 0) return;

    int b0 = b / 144, r = b - b0*144, b1 = r / 12, b2 = r - b1*12;
    int d0lo = b0 > 0 ? b0-1 : 0, d0hi = b0 < 11 ? b0+1 : 11;
    int d1lo = b1 > 0 ? b1-1 : 0, d1hi = b1 < 11 ? b1+1 : 11;
    int d2lo = b2 > 0 ? b2-1 : 0, d2hi = b2 < 11 ? b2+1 : 11;

    // stage candidates (order identical to the dense scan: bin-major, CSR order)
    int pos = 0;
    for (int d0 = d0lo; d0 <= d0hi; d0++)
    for (int d1 = d1lo; d1 <= d1hi; d1++)
    for (int d2 = d2lo; d2 <= d2hi; d2++) {
        int nbin = (d0*NBIN + d1)*NBIN + d2;
        int s = g_binstart[nbin], c = g_bincnt[nbin];
        if (pos + c > SCAP) c = SCAP - pos;
        for (int t = threadIdx.x; t < c; t += 128) {
            int j = g_binpts[s + t];
            float4 col = g_col[j];
            sj[pos + t] = j;
            s0[pos + t] = col.x; s1[pos + t] = col.y; s2[pos + t] = col.z;
        }
        pos += c;
    }
    __syncthreads();

    const int lane = threadIdx.x & 31;
    const int w    = threadIdx.x >> 5;
    const int mybase = g_binstart[b];

    for (int p = w; p < cnt; p += 4) {
        int i = g_binpts[mybase + p];
        float4 ci = g_col[i];
        int iz = i >> 10, iy = (i >> 5) & 31, ix = i & 31;
        int   acc = 0;
        float nb  = 0.f;
        for (int base = 0; base < pos; base += 32) {
            int idx = base + lane;
            float ev = 1e30f; int j = 0;
            if (idx < pos) {
                j = sj[idx];
                float dz = (float)(iz - (j >> 10));
                float dy = (float)(iy - ((j >> 5) & 31));
                float dx = (float)(ix - (j & 31));
                float u3 = ci.x - s0[idx];
                float u4 = ci.y - s1[idx];
                float u5 = ci.z - s2[idx];
                ev = (dz*dz + dy*dy + dx*dx) * (SA*SA) + u3*u3 + u4*u4 + u5*u5;
            }
            bool a = (ev <= ECUT);
            unsigned m = __ballot_sync(0xffffffffu, a);
            if (a) {
                int off = acc + __popc(m & ((1u << lane) - 1u));
                if (off < CAP) {
                    float kv = __expf(-ev);
                    g_nidx[i*CAP + off] = j;
                    g_nval[i*CAP + off] = kv;
                    nb += kv;
                }
            }
            acc += __popc(m);
        }
        for (int o = 16; o; o >>= 1) nb += __shfl_xor_sync(0xffffffffu, nb, o);
        if (acc > CAP) acc = CAP;
        if (lane == 0) { g_ncnt[i] = acc; g_nbi[i] = nb; }
    }
}

// ---------------------------------------------------------------------------
// Initial softmax: logits (L,N) -> qT (N,LP)
// ---------------------------------------------------------------------------
__global__ void k_softmax0(const float* __restrict__ logits)
{
    int i = blockIdx.x * blockDim.x + threadIdx.x;    // 8192
    float v[LL];
    float mx = -1e30f;
    #pragma unroll
    for (int l = 0; l < LL; l++) { v[l] = logits[l*NPIX + i]; mx = fmaxf(mx, v[l]); }
    float s = 0.f;
    #pragma unroll
    for (int l = 0; l < LL; l++) { v[l] = __expf(v[l] - mx); s += v[l]; }
    float inv = 1.0f / s;
    #pragma unroll
    for (int l = 0; l < LL; l++) g_qT[i*LP + l] = v[l] * inv;
    g_qT[i*LP + 21] = 0.f; g_qT[i*LP + 22] = 0.f; g_qT[i*LP + 23] = 0.f;
}

// ---------------------------------------------------------------------------
// Phase B: z-conv (blocks [0,768)) + sparse bilateral gather (blocks [768,1792))
// ---------------------------------------------------------------------------
__global__ void k_zb()
{
    if (blockIdx.x < 768) {
        int e = blockIdx.x * 256 + threadIdx.x;       // < NPIX*LP
        int i = e / LP, l = e - i*LP;
        int zbase = i & 1023;
        int z = i >> 10;
        float acc = 0.f;
        #pragma unroll
        for (int zp = 0; zp < DD; zp++)
            acc += g_kg[z*32 + zp] * g_qT[((zp << 10) | zbase)*LP + l];
        g_t1[e] = acc;
    } else {
        int w    = ((blockIdx.x - 768) * 256 + threadIdx.x) >> 5;  // pixel
        int lane = threadIdx.x & 31;
        if (lane >= LP) return;
        int cnt  = g_ncnt[w];
        const int*   ip = &g_nidx[w*CAP];
        const float* vp = &g_nval[w*CAP];
        float acc = 0.f;
        int n = 0;
        for (; n + 4 <= cnt; n += 4) {
            int   j0 = ip[n],   j1 = ip[n+1], j2 = ip[n+2], j3 = ip[n+3];
            float k0 = vp[n],   k1 = vp[n+1], k2 = vp[n+2], k3 = vp[n+3];
            float a0 = g_qT[j0*LP + lane], a1 = g_qT[j1*LP + lane];
            float a2 = g_qT[j2*LP + lane], a3 = g_qT[j3*LP + lane];
            acc += k0*a0; acc += k1*a1; acc += k2*a2; acc += k3*a3;
        }
        for (; n < cnt; n++) acc += vp[n] * g_qT[ip[n]*LP + lane];
        g_bi[w*LP + lane] = acc;
    }
}

// ---------------------------------------------------------------------------
// Phase C: y-conv. CTA per (z,x) column, threads (y,l).
// ---------------------------------------------------------------------------
__global__ void k_convy()
{
    __shared__ float sh[32*LP];
    int z = blockIdx.x >> 5, x = blockIdx.x & 31;
    int tid = threadIdx.x;                 // 768
    int y = tid / LP, l = tid - y*LP;
    int i = (z << 10) + (y << 5) + x;
    sh[tid] = g_t1[i*LP + l];
    __syncthreads();
    float acc = 0.f;
    const float* kr = &g_kg[y*32];
    #pragma unroll 8
    for (int yp = 0; yp < 32; yp++) acc += kr[yp] * sh[yp*LP + l];
    g_t2[i*LP + l] = acc;
}

// ---------------------------------------------------------------------------
// Phase D: x-conv + normalize + L x L mixing + cur = unary + msg + softmax.
// CTA per (z,y) row, threads (x,l). One exp per thread (shared-sum softmax).
// ---------------------------------------------------------------------------
__global__ void k_final(const float* __restrict__ unary, float* __restrict__ out,
                        int last)
{
    __shared__ float sh[32*LP];
    __shared__ float sc[32*LP];
    __shared__ float wsp[LL*LL], wbi[LL*LL];
    int z = blockIdx.x >> 5, y = blockIdx.x & 31;
    int tid = threadIdx.x;                 // 768
    int x = tid / LP, l = tid - x*LP;
    for (int e = tid; e < LL*LL; e += 768) { wsp[e] = g_CWsp[e]; wbi[e] = g_CWbi[e]; }
    int i = (z << 10) + (y << 5) + x;
    sh[tid] = g_t2[i*LP + l];
    __syncthreads();

    float sp = 0.f;
    {
        const float* kr = &g_kg[x*32];
        #pragma unroll 8
        for (int xp = 0; xp < 32; xp++) sp += kr[xp] * sh[xp*LP + l];
    }
    float nsp = g_sz[z] * g_syx[y] * g_syx[x];
    float nbi = g_nbi[i];
    __syncthreads();
    sh[tid] = sp / nsp;
    sc[tid] = g_bi[i*LP + l] / nbi;
    __syncthreads();

    float cur = -1e30f;
    if (l < LL) {
        float msg = 0.f;
        #pragma unroll
        for (int m = 0; m < LL; m++)
            msg += wsp[l*LL + m] * sh[x*LP + m] + wbi[l*LL + m] * sc[x*LP + m];
        cur = unary[l*NPIX + i] + msg;
    }
    __syncthreads();
    sh[tid] = cur;
    __syncthreads();

    float mx = -1e30f;
    #pragma unroll
    for (int m = 0; m < LL; m++) mx = fmaxf(mx, sh[x*LP + m]);
    float e = __expf(cur - mx);            // one exp per thread; 0 for l>=21
    __syncthreads();
    sc[tid] = e;
    __syncthreads();
    float se = 0.f;
    #pragma unroll
    for (int m = 0; m < LL; m++) se += sc[x*LP + m];
    float q = e / se;
    g_qT[i*LP + l] = (l < LL) ? q : 0.f;
    if (last && l < LL) out[l*NPIX + i] = q;
}

// ---------------------------------------------------------------------------
extern "C" void kernel_launch(void* const* d_in, const int* in_sizes, int n_in,
                              void* d_out, int out_size)
{
    (void)in_sizes; (void)n_in; (void)out_size;
    const float* image  = (const float*)d_in[0];
    const float* logits = (const float*)d_in[1];
    const float* unary  = (const float*)d_in[2];
    const float* Wsp    = (const float*)d_in[3];
    const float* Wbi    = (const float*)d_in[4];
    const float* C      = (const float*)d_in[5];
    float* out = (float*)d_out;

    k_setup<<<1, 1024>>>(image, Wsp, Wbi, C);
    k_build<<<NBIN3, 128>>>();
    k_softmax0<<<64, 128>>>(logits);
    for (int it = 0; it < NITER; it++) {
        k_zb<<<1792, 256>>>();
        k_convy<<<256, 768>>>();
        k_final<<<256, 768>>>(unary, out, it == NITER - 1);
    }
}

// round 3
// speedup vs baseline: 1.1587x; 1.0007x over previous
#include <cuda_runtime.h>
#include <stdint.h>

// ---------------------------------------------------------------------------
// DenseCRF mean-field:
//   * exact separability of the spatial Gaussian kernel (3 x 1-D convs)
//   * extreme color-sparsity of the bilateral kernel (beta=3, uniform colors)
// R2: cooperative per-bin sparse build (226MB -> 3.5MB gather traffic),
//     single-exp softmax in k_final, unrolled bilateral gather.
// ---------------------------------------------------------------------------

#define NPIX   8192          // D*H*W = 8*32*32
#define DD     8
#define LL     21
#define LP     24            // padded label count
#define NITER  5
#define NBIN   12
#define NBIN3  1728          // 12^3
#define CAP    128           // max sparse neighbors per pixel (expected ~17)
#define SCAP   2048          // candidate staging capacity per bin neighborhood
#define ECUT   23.0f         // drop bilateral terms with exponent > 23 (k < 1e-10)

#define SA (1.0f/(160.0f*1.41421356237f))   // pos scale: 1/(alpha*sqrt(2))
#define SB (1.0f/(3.0f*1.41421356237f))     // color scale: 1/(beta*sqrt(2))

// ------------------------------- scratch -----------------------------------
__device__ float4 g_col[NPIX];         // scaled colors (c*SB), w unused
__device__ int    g_binid[NPIX];
__device__ int    g_binstart[NBIN3];
__device__ int    g_bincnt[NBIN3];
__device__ int    g_binpts[NPIX];
__device__ int    g_nidx[NPIX*CAP];    // sparse bilateral neighbor indices
__device__ float  g_nval[NPIX*CAP];    // sparse bilateral kernel values
__device__ int    g_ncnt[NPIX];
__device__ float  g_nbi[NPIX];         // bilateral normalizer (row sum)
__device__ float  g_qT[NPIX*LP];       // probabilities, pixel-major padded
__device__ float  g_t1[NPIX*LP];       // after z-conv
__device__ float  g_t2[NPIX*LP];       // after y-conv
__device__ float  g_bi[NPIX*LP];       // bilateral message (un-normalized)
__device__ float  g_CWsp[LL*LL];       // compat @ spatial_weights
__device__ float  g_CWbi[LL*LL];       // compat @ bilateral_weights
__device__ float  g_kg[32*32];         // 1-D Gaussian LUT exp(-0.5*((a-b)/3)^2)
__device__ float  g_sz[8];             // tap sums (z)
__device__ float  g_syx[32];           // tap sums (y / x)

// ---------------------------------------------------------------------------
// Setup: CW matrices, Gaussian LUT + sums, scaled colors, color-bin CSR
// (counts via integer shared atomics, scatter via deterministic warp ranking)
// ---------------------------------------------------------------------------
__global__ void k_setup(const float* __restrict__ image,
                        const float* __restrict__ Wsp,
                        const float* __restrict__ Wbi,
                        const float* __restrict__ C)
{
    __shared__ int scnt[NBIN3];
    __shared__ int csum[28];
    const int tid = threadIdx.x;                 // 1024 threads

    // CWsp = C @ Wsp, CWbi = C @ Wbi   (21x21 each)
    for (int e = tid; e < LL*LL; e += 1024) {
        int l = e / LL, m = e - l*LL;
        float a = 0.f, b = 0.f;
        for (int k = 0; k < LL; k++) {
            float c = C[l*LL + k];
            a += c * Wsp[k*LL + m];
            b += c * Wbi[k*LL + m];
        }
        g_CWsp[e] = a; g_CWbi[e] = b;
    }
    // 1-D Gaussian LUT
    {
        int a = tid >> 5, b = tid & 31;
        float d = (float)(a - b) * (1.0f/3.0f);
        g_kg[tid] = __expf(-0.5f * d * d);
    }
    for (int e = tid; e < NBIN3; e += 1024) scnt[e] = 0;
    __syncthreads();

    if (tid < 32) {
        float s = 0.f;
        for (int b = 0; b < 32; b++) s += g_kg[tid*32 + b];
        g_syx[tid] = s;
    } else if (tid < 40) {
        int a = tid - 32;
        float s = 0.f;
        for (int b = 0; b < 8; b++) s += g_kg[a*32 + b];
        g_sz[a] = s;
    }

    // scaled colors + bin ids + bin counts
    for (int i = tid; i < NPIX; i += 1024) {
        float c0 = image[i], c1 = image[NPIX + i], c2 = image[2*NPIX + i];
        g_col[i] = make_float4(c0*SB, c1*SB, c2*SB, 0.f);
        int b0 = (int)(c0 * (12.0f/255.0f)); b0 = b0 < 0 ? 0 : (b0 > 11 ? 11 : b0);
        int b1 = (int)(c1 * (12.0f/255.0f)); b1 = b1 < 0 ? 0 : (b1 > 11 ? 11 : b1);
        int b2 = (int)(c2 * (12.0f/255.0f)); b2 = b2 < 0 ? 0 : (b2 > 11 ? 11 : b2);
        int bin = (b0*NBIN + b1)*NBIN + b2;
        g_binid[i] = bin;
        atomicAdd(&scnt[bin], 1);
    }
    __syncthreads();

    // prefix: 27 chunks of 64
    if (tid < 27) {
        int s = 0;
        for (int k = 0; k < 64; k++) s += scnt[tid*64 + k];
        csum[tid] = s;
    }
    __syncthreads();
    if (tid == 0) {
        int s = 0;
        for (int c = 0; c < 27; c++) { int t = csum[c]; csum[c] = s; s += t; }
    }
    __syncthreads();
    for (int b = tid; b < NBIN3; b += 1024) {
        int chunk = b >> 6;
        int s = csum[chunk];
        for (int k = chunk*64; k < b; k++) s += scnt[k];
        g_binstart[b] = s;
        g_bincnt[b]   = scnt[b];
    }
    __syncthreads();
    for (int e = tid; e < NBIN3; e += 1024) scnt[e] = 0;  // reuse as cursors
    __syncthreads();

    // deterministic scatter: warp 0 processes pixels in fixed order
    if (tid < 32) {
        for (int base = 0; base < NPIX; base += 32) {
            int i = base + tid;
            int b = g_binid[i];
            unsigned m = __match_any_sync(0xffffffffu, b);
            int rank = __popc(m & ((1u << tid) - 1u));
            int leader = __ffs(m) - 1;
            int cur = scnt[b];
            g_binpts[g_binstart[b] + cur + rank] = i;
            __syncwarp();
            if (tid == leader) scnt[b] = cur + __popc(m);
            __syncwarp();
        }
    }
}

// ---------------------------------------------------------------------------
// Build sparse bilateral rows, cooperatively per bin: stage the shared 27-bin
// candidate neighborhood in SMEM once, then each warp tests one member pixel.
// Positions recovered from pixel index (no feature gather).
// ---------------------------------------------------------------------------
__global__ void k_build()
{
    __shared__ int   sj[SCAP];
    __shared__ float s0[SCAP], s1[SCAP], s2[SCAP];
    const int b   = blockIdx.x;
    const int cnt = g_bincnt[b];
    if (cnt == 0) return;

    int b0 = b / 144, r = b - b0*144, b1 = r / 12, b2 = r - b1*12;
    int d0lo = b0 > 0 ? b0-1 : 0, d0hi = b0 < 11 ? b0+1 : 11;
    int d1lo = b1 > 0 ? b1-1 : 0, d1hi = b1 < 11 ? b1+1 : 11;
    int d2lo = b2 > 0 ? b2-1 : 0, d2hi = b2 < 11 ? b2+1 : 11;

    // stage candidates (order identical to the dense scan: bin-major, CSR order)
    int pos = 0;
    for (int d0 = d0lo; d0 <= d0hi; d0++)
    for (int d1 = d1lo; d1 <= d1hi; d1++)
    for (int d2 = d2lo; d2 <= d2hi; d2++) {
        int nbin = (d0*NBIN + d1)*NBIN + d2;
        int s = g_binstart[nbin], c = g_bincnt[nbin];
        if (pos + c > SCAP) c = SCAP - pos;
        for (int t = threadIdx.x; t < c; t += 128) {
            int j = g_binpts[s + t];
            float4 col = g_col[j];
            sj[pos + t] = j;
            s0[pos + t] = col.x; s1[pos + t] = col.y; s2[pos + t] = col.z;
        }
        pos += c;
    }
    __syncthreads();

    const int lane = threadIdx.x & 31;
    const int w    = threadIdx.x >> 5;
    const int mybase = g_binstart[b];

    for (int p = w; p < cnt; p += 4) {
        int i = g_binpts[mybase + p];
        float4 ci = g_col[i];
        int iz = i >> 10, iy = (i >> 5) & 31, ix = i & 31;
        int   acc = 0;
        float nb  = 0.f;
        for (int base = 0; base < pos; base += 32) {
            int idx = base + lane;
            float ev = 1e30f; int j = 0;
            if (idx < pos) {
                j = sj[idx];
                float dz = (float)(iz - (j >> 10));
                float dy = (float)(iy - ((j >> 5) & 31));
                float dx = (float)(ix - (j & 31));
                float u3 = ci.x - s0[idx];
                float u4 = ci.y - s1[idx];
                float u5 = ci.z - s2[idx];
                ev = (dz*dz + dy*dy + dx*dx) * (SA*SA) + u3*u3 + u4*u4 + u5*u5;
            }
            bool a = (ev <= ECUT);
            unsigned m = __ballot_sync(0xffffffffu, a);
            if (a) {
                int off = acc + __popc(m & ((1u << lane) - 1u));
                if (off < CAP) {
                    float kv = __expf(-ev);
                    g_nidx[i*CAP + off] = j;
                    g_nval[i*CAP + off] = kv;
                    nb += kv;
                }
            }
            acc += __popc(m);
        }
        for (int o = 16; o; o >>= 1) nb += __shfl_xor_sync(0xffffffffu, nb, o);
        if (acc > CAP) acc = CAP;
        if (lane == 0) { g_ncnt[i] = acc; g_nbi[i] = nb; }
    }
}

// ---------------------------------------------------------------------------
// Initial softmax: logits (L,N) -> qT (N,LP)
// ---------------------------------------------------------------------------
__global__ void k_softmax0(const float* __restrict__ logits)
{
    int i = blockIdx.x * blockDim.x + threadIdx.x;    // 8192
    float v[LL];
    float mx = -1e30f;
    #pragma unroll
    for (int l = 0; l < LL; l++) { v[l] = logits[l*NPIX + i]; mx = fmaxf(mx, v[l]); }
    float s = 0.f;
    #pragma unroll
    for (int l = 0; l < LL; l++) { v[l] = __expf(v[l] - mx); s += v[l]; }
    float inv = 1.0f / s;
    #pragma unroll
    for (int l = 0; l < LL; l++) g_qT[i*LP + l] = v[l] * inv;
    g_qT[i*LP + 21] = 0.f; g_qT[i*LP + 22] = 0.f; g_qT[i*LP + 23] = 0.f;
}

// ---------------------------------------------------------------------------
// Phase B: z-conv (blocks [0,768)) + sparse bilateral gather (blocks [768,1792))
// ---------------------------------------------------------------------------
__global__ void k_zb()
{
    if (blockIdx.x < 768) {
        int e = blockIdx.x * 256 + threadIdx.x;       // < NPIX*LP
        int i = e / LP, l = e - i*LP;
        int zbase = i & 1023;
        int z = i >> 10;
        float acc = 0.f;
        #pragma unroll
        for (int zp = 0; zp < DD; zp++)
            acc += g_kg[z*32 + zp] * g_qT[((zp << 10) | zbase)*LP + l];
        g_t1[e] = acc;
    } else {
        int w    = ((blockIdx.x - 768) * 256 + threadIdx.x) >> 5;  // pixel
        int lane = threadIdx.x & 31;
        if (lane >= LP) return;
        int cnt  = g_ncnt[w];
        const int*   ip = &g_nidx[w*CAP];
        const float* vp = &g_nval[w*CAP];
        float acc = 0.f;
        int n = 0;
        for (; n + 4 <= cnt; n += 4) {
            int   j0 = ip[n],   j1 = ip[n+1], j2 = ip[n+2], j3 = ip[n+3];
            float k0 = vp[n],   k1 = vp[n+1], k2 = vp[n+2], k3 = vp[n+3];
            float a0 = g_qT[j0*LP + lane], a1 = g_qT[j1*LP + lane];
            float a2 = g_qT[j2*LP + lane], a3 = g_qT[j3*LP + lane];
            acc += k0*a0; acc += k1*a1; acc += k2*a2; acc += k3*a3;
        }
        for (; n < cnt; n++) acc += vp[n] * g_qT[ip[n]*LP + lane];
        g_bi[w*LP + lane] = acc;
    }
}

// ---------------------------------------------------------------------------
// Phase C: y-conv. CTA per (z,x) column, threads (y,l).
// ---------------------------------------------------------------------------
__global__ void k_convy()
{
    __shared__ float sh[32*LP];
    int z = blockIdx.x >> 5, x = blockIdx.x & 31;
    int tid = threadIdx.x;                 // 768
    int y = tid / LP, l = tid - y*LP;
    int i = (z << 10) + (y << 5) + x;
    sh[tid] = g_t1[i*LP + l];
    __syncthreads();
    float acc = 0.f;
    const float* kr = &g_kg[y*32];
    #pragma unroll 8
    for (int yp = 0; yp < 32; yp++) acc += kr[yp] * sh[yp*LP + l];
    g_t2[i*LP + l] = acc;
}

// ---------------------------------------------------------------------------
// Phase D: x-conv + normalize + L x L mixing + cur = unary + msg + softmax.
// CTA per (z,y) row, threads (x,l). One exp per thread (shared-sum softmax).
// ---------------------------------------------------------------------------
__global__ void k_final(const float* __restrict__ unary, float* __restrict__ out,
                        int last)
{
    __shared__ float sh[32*LP];
    __shared__ float sc[32*LP];
    __shared__ float wsp[LL*LL], wbi[LL*LL];
    int z = blockIdx.x >> 5, y = blockIdx.x & 31;
    int tid = threadIdx.x;                 // 768
    int x = tid / LP, l = tid - x*LP;
    for (int e = tid; e < LL*LL; e += 768) { wsp[e] = g_CWsp[e]; wbi[e] = g_CWbi[e]; }
    int i = (z << 10) + (y << 5) + x;
    sh[tid] = g_t2[i*LP + l];
    __syncthreads();

    float sp = 0.f;
    {
        const float* kr = &g_kg[x*32];
        #pragma unroll 8
        for (int xp = 0; xp < 32; xp++) sp += kr[xp] * sh[xp*LP + l];
    }
    float nsp = g_sz[z] * g_syx[y] * g_syx[x];
    float nbi = g_nbi[i];
    __syncthreads();
    sh[tid] = sp / nsp;
    sc[tid] = g_bi[i*LP + l] / nbi;
    __syncthreads();

    float cur = -1e30f;
    if (l < LL) {
        float msg = 0.f;
        #pragma unroll
        for (int m = 0; m < LL; m++)
            msg += wsp[l*LL + m] * sh[x*LP + m] + wbi[l*LL + m] * sc[x*LP + m];
        cur = unary[l*NPIX + i] + msg;
    }
    __syncthreads();
    sh[tid] = cur;
    __syncthreads();

    float mx = -1e30f;
    #pragma unroll
    for (int m = 0; m < LL; m++) mx = fmaxf(mx, sh[x*LP + m]);
    float e = __expf(cur - mx);            // one exp per thread; 0 for l>=21
    __syncthreads();
    sc[tid] = e;
    __syncthreads();
    float se = 0.f;
    #pragma unroll
    for (int m = 0; m < LL; m++) se += sc[x*LP + m];
    float q = e / se;
    g_qT[i*LP + l] = (l < LL) ? q : 0.f;
    if (last && l < LL) out[l*NPIX + i] = q;
}

// ---------------------------------------------------------------------------
extern "C" void kernel_launch(void* const* d_in, const int* in_sizes, int n_in,
                              void* d_out, int out_size)
{
    (void)in_sizes; (void)n_in; (void)out_size;
    const float* image  = (const float*)d_in[0];
    const float* logits = (const float*)d_in[1];
    const float* unary  = (const float*)d_in[2];
    const float* Wsp    = (const float*)d_in[3];
    const float* Wbi    = (const float*)d_in[4];
    const float* C      = (const float*)d_in[5];
    float* out = (float*)d_out;

    k_setup<<<1, 1024>>>(image, Wsp, Wbi, C);
    k_build<<<NBIN3, 128>>>();
    k_softmax0<<<64, 128>>>(logits);
    for (int it = 0; it < NITER; it++) {
        k_zb<<<1792, 256>>>();
        k_convy<<<256, 768>>>();
        k_final<<<256, 768>>>(unary, out, it == NITER - 1);
    }
}